// round 2
// baseline (speedup 1.0000x reference)
#include <cuda_runtime.h>
#include <math.h>

// ---------------- problem constants ----------------
#define NP 2048        // pairs
#define NN 4096        // X/Y rows
#define DF 256         // latent dim
#define DX 768         // X dim
#define DY 512         // Y dim
#define CLAMPF 1e-8f
#define EPS_INV 20.0f  // 1/0.05

// ---------------- static device scratch ----------------
__device__ float g_Xa[NN*DX];
__device__ float g_Ya[NN*DY];
__device__ float g_Sxx[DX*DX];
__device__ float g_Syy[DY*DY];
__device__ float g_Sxy[DX*DY];
__device__ float g_fXp[NP*DF];
__device__ float g_fYp[NP*DF];
__device__ float g_Mp[(size_t)NP*NP];
__device__ float g_Pp[(size_t)NP*NP];
__device__ float g_fXn[NN*DF];
__device__ float g_fYn[NN*DF];
__device__ float g_Mu[(size_t)NN*NN];
__device__ float g_Ma[(size_t)NN*NN];
__device__ float g_P [(size_t)NN*NN];
__device__ float g_XS[NN*DX];   // X@Sxx, later reused as diag(a)*Xu
__device__ float g_YS[NN*DY];   // Y@Syy, later reused as diag(b)*Yu
__device__ float g_Xn[NN*DX];
__device__ float g_Yn[NN*DY];
__device__ float g_Xu[NN*DX];
__device__ float g_Yu[NN*DY];
__device__ float g_T [NN*DY];   // Xn@Sxy, later reused as P@Yu
__device__ float g_Cxx[DX*DX];
__device__ float g_Cyy[DY*DY];
__device__ float g_U1[DX*DY];
__device__ float g_V1[DX*DY];
__device__ float g_Fxx[DF*DF];
__device__ float g_Fyy[DF*DF];
__device__ float g_W1[DX*DF];
__device__ float g_W2[DF*DY];
__device__ float g_W3[DX*DY];
__device__ float g_MA[DX*DX];   // MAx, then MAy, then G (sequential reuse)
__device__ float g_u1[NP], g_v1[NP];      // sinkhorn pairs
__device__ float g_u2[NN], g_v2[NN];      // sinkhorn latent
__device__ float g_u3[NN], g_v3[NN];      // sinkhorn anchor
__device__ float g_pm[64*NN], g_ps[64*NN];// col-LSE partials
__device__ float g_rsp[NP], g_csp[NP];    // plan_p marginals
__device__ float g_a[NN], g_b[NN];        // plan_u marginals
__device__ double g_acc[16];

// acc slots:
// 0: L_marg  1: sail-sum  2: exp-diag-sum  3: imp-diag-logp-sum
// 4: L_ot    5: norm1     6: norm2         7: dot
// 8: frob(MAx) 9: frob(MAy) 10: frob(G)

// ---------------- reduction helper ----------------
__device__ __forceinline__ float blockReduceSum(float v) {
    __shared__ float sh[32];
    __syncthreads();                       // protect prior use of sh
    int lane = threadIdx.x & 31, wid = threadIdx.x >> 5;
    #pragma unroll
    for (int o = 16; o > 0; o >>= 1) v += __shfl_down_sync(0xffffffffu, v, o);
    if (lane == 0) sh[wid] = v;
    __syncthreads();
    int nw = blockDim.x >> 5;
    v = (threadIdx.x < nw) ? sh[threadIdx.x] : 0.f;
    if (wid == 0) {
        #pragma unroll
        for (int o = 16; o > 0; o >>= 1) v += __shfl_down_sync(0xffffffffu, v, o);
    }
    return v;  // valid on thread 0
}

// ---------------- elementwise / norms ----------------
__global__ void k_zero_acc() { if (threadIdx.x < 16) g_acc[threadIdx.x] = 0.0; }

__global__ void k_zero_vec(float* v, int n) {
    int i = blockIdx.x * blockDim.x + threadIdx.x;
    if (i < n) v[i] = 0.f;
}

__global__ void k_rownorm(const float* __restrict__ in, float* __restrict__ out, int cols) {
    int row = blockIdx.x;
    const float* r = in + (size_t)row * cols;
    float ss = 0.f;
    for (int c = threadIdx.x; c < cols; c += blockDim.x) { float x = r[c]; ss += x * x; }
    float tot = blockReduceSum(ss);
    __shared__ float sInv;
    if (threadIdx.x == 0) sInv = 1.f / fmaxf(sqrtf(tot), CLAMPF);
    __syncthreads();
    float inv = sInv;
    float* o = out + (size_t)row * cols;
    for (int c = threadIdx.x; c < cols; c += blockDim.x) o[c] = r[c] * inv;
}

// Xn = X / clamp(sqrt(rowdot(X, XS)))
__global__ void k_metricnorm(const float* __restrict__ X, const float* __restrict__ XS,
                             float* __restrict__ Xn, int cols) {
    int row = blockIdx.x;
    const float* r  = X  + (size_t)row * cols;
    const float* rs = XS + (size_t)row * cols;
    float ss = 0.f;
    for (int c = threadIdx.x; c < cols; c += blockDim.x) ss += r[c] * rs[c];
    float tot = blockReduceSum(ss);
    __shared__ float sInv;
    if (threadIdx.x == 0) sInv = 1.f / fmaxf(sqrtf(tot), CLAMPF);
    __syncthreads();
    float inv = sInv;
    float* o = Xn + (size_t)row * cols;
    for (int c = threadIdx.x; c < cols; c += blockDim.x) o[c] = r[c] * inv;
}

__global__ void k_rowscale(const float* __restrict__ in, const float* __restrict__ s,
                           float* __restrict__ out, int C, size_t n) {
    for (size_t idx = (size_t)blockIdx.x * blockDim.x + threadIdx.x; idx < n;
         idx += (size_t)gridDim.x * blockDim.x) {
        int i = (int)(idx / C);
        out[idx] = in[idx] * s[i];
    }
}

// ---------------- GEMM: C = alpha * op(A) @ op(B) ----------------
// logical A is MxK: TA ? stored KxM : stored MxK (row-major)
// logical B is KxN: TB ? stored NxK : stored KxN
// All M,N multiples of 128; K multiple of 8.
// 128x128 tile, 256 threads, 8x8 microtile.
template<bool TA, bool TB>
__global__ void __launch_bounds__(256, 1)
k_gemm(const float* __restrict__ A, const float* __restrict__ B,
       float* __restrict__ C, int M, int N, int K, float alpha) {
    __shared__ float As[8][132];   // pad 4: k-fast stores hit distinct banks
    __shared__ float Bs[8][132];
    int bm = blockIdx.y * 128, bn = blockIdx.x * 128;
    int tid = threadIdx.x;
    int tx = tid & 15, ty = tid >> 4;   // 16x16 threads
    float acc[8][8];
    #pragma unroll
    for (int i = 0; i < 8; i++)
        #pragma unroll
        for (int j = 0; j < 8; j++) acc[i][j] = 0.f;

    for (int k0 = 0; k0 < K; k0 += 8) {
        // ---- load A tile: As[k][m], k in [0,8), m in [0,128) ----
        if (!TA) {
            int k = tid & 7, m0 = tid >> 3;        // m0: 0..31
            #pragma unroll
            for (int r = 0; r < 4; r++) {
                int m = m0 + r * 32;
                As[k][m] = A[(size_t)(bm + m) * K + (k0 + k)];
            }
        } else {
            #pragma unroll
            for (int r = 0; r < 4; r++) {
                int idx = tid + r * 256;
                int k = idx >> 7, m = idx & 127;   // coalesced over m
                As[k][m] = A[(size_t)(k0 + k) * M + (bm + m)];
            }
        }
        // ---- load B tile: Bs[k][n] ----
        if (!TB) {
            #pragma unroll
            for (int r = 0; r < 4; r++) {
                int idx = tid + r * 256;
                int k = idx >> 7, n = idx & 127;   // coalesced over n
                Bs[k][n] = B[(size_t)(k0 + k) * N + (bn + n)];
            }
        } else {
            int k = tid & 7, n0 = tid >> 3;
            #pragma unroll
            for (int r = 0; r < 4; r++) {
                int n = n0 + r * 32;
                Bs[k][n] = B[(size_t)(bn + n) * K + (k0 + k)];
            }
        }
        __syncthreads();
        #pragma unroll
        for (int k = 0; k < 8; k++) {
            float ra[8], rb[8];
            #pragma unroll
            for (int i = 0; i < 8; i++) ra[i] = As[k][ty * 8 + i];
            #pragma unroll
            for (int j = 0; j < 8; j++) rb[j] = Bs[k][tx * 8 + j];
            #pragma unroll
            for (int i = 0; i < 8; i++)
                #pragma unroll
                for (int j = 0; j < 8; j++) acc[i][j] = fmaf(ra[i], rb[j], acc[i][j]);
        }
        __syncthreads();
    }
    #pragma unroll
    for (int i = 0; i < 8; i++) {
        int gm = bm + ty * 8 + i;
        float* cp = &C[(size_t)gm * N + bn + tx * 8];
        float4 o0 = make_float4(alpha * acc[i][0], alpha * acc[i][1],
                                alpha * acc[i][2], alpha * acc[i][3]);
        float4 o1 = make_float4(alpha * acc[i][4], alpha * acc[i][5],
                                alpha * acc[i][6], alpha * acc[i][7]);
        reinterpret_cast<float4*>(cp)[0] = o0;
        reinterpret_cast<float4*>(cp)[1] = o1;
    }
}

// ---------------- Sinkhorn (log-domain, online LSE) ----------------
__global__ void k_row_lse(const float* __restrict__ M, const float* __restrict__ v,
                          float* __restrict__ u, int C, float log_a) {
    int row = blockIdx.x;
    const float* r = M + (size_t)row * C;
    float m = -1e30f, s = 0.f;
    for (int c = threadIdx.x; c < C; c += blockDim.x) {
        float x = r[c] + v[c];
        if (x > m) { s = s * __expf(m - x) + 1.f; m = x; }
        else s += __expf(x - m);
    }
    __shared__ float shm[256], shs[256];
    shm[threadIdx.x] = m; shs[threadIdx.x] = s;
    __syncthreads();
    for (int off = blockDim.x >> 1; off > 0; off >>= 1) {
        if (threadIdx.x < off) {
            float m1 = shm[threadIdx.x], s1 = shs[threadIdx.x];
            float m2 = shm[threadIdx.x + off], s2 = shs[threadIdx.x + off];
            float mm = fmaxf(m1, m2);
            shm[threadIdx.x] = mm;
            shs[threadIdx.x] = s1 * __expf(m1 - mm) + s2 * __expf(m2 - mm);
        }
        __syncthreads();
    }
    if (threadIdx.x == 0) u[row] = log_a - (shm[0] + logf(shs[0]));
}

__global__ void k_col_lse_part(const float* __restrict__ M, const float* __restrict__ u,
                               float* __restrict__ pm, float* __restrict__ ps,
                               int C, int chunk) {
    int col = blockIdx.x * blockDim.x + threadIdx.x;
    int r0 = blockIdx.y * chunk;
    float m = -1e30f, s = 0.f;
    for (int r = r0; r < r0 + chunk; r++) {
        float x = M[(size_t)r * C + col] + u[r];
        if (x > m) { s = s * __expf(m - x) + 1.f; m = x; }
        else s += __expf(x - m);
    }
    pm[(size_t)blockIdx.y * C + col] = m;
    ps[(size_t)blockIdx.y * C + col] = s;
}

__global__ void k_col_lse_comb(const float* __restrict__ pm, const float* __restrict__ ps,
                               float* __restrict__ v, int C, int splits, float log_b) {
    int col = blockIdx.x * blockDim.x + threadIdx.x;
    if (col >= C) return;
    float m = -1e30f, s = 0.f;
    for (int k = 0; k < splits; k++) {
        float m2 = pm[(size_t)k * C + col], s2 = ps[(size_t)k * C + col];
        float mm = fmaxf(m, m2);
        s = s * __expf(m - mm) + s2 * __expf(m2 - mm);
        m = mm;
    }
    v[col] = log_b - (m + logf(s));
}

// P = exp(M + u_i + v_j); shift/mask for pow2 column count
__global__ void k_plan(const float* __restrict__ M, const float* __restrict__ u,
                       const float* __restrict__ v, float* __restrict__ P,
                       int shift, int mask, size_t n) {
    for (size_t idx = (size_t)blockIdx.x * blockDim.x + threadIdx.x; idx < n;
         idx += (size_t)gridDim.x * blockDim.x) {
        int i = (int)(idx >> shift), j = (int)(idx & mask);
        P[idx] = __expf(M[idx] + u[i] + v[j]);
    }
}

__global__ void k_rowsum(const float* __restrict__ P, float* __restrict__ rs, int C) {
    int row = blockIdx.x;
    const float* r = P + (size_t)row * C;
    float s = 0.f;
    for (int c = threadIdx.x; c < C; c += blockDim.x) s += r[c];
    float tot = blockReduceSum(s);
    if (threadIdx.x == 0) rs[row] = tot;
}

__global__ void k_colsum_part(const float* __restrict__ P, float* __restrict__ part,
                              int C, int chunk) {
    int col = blockIdx.x * blockDim.x + threadIdx.x;
    int r0 = blockIdx.y * chunk;
    float s = 0.f;
    for (int r = r0; r < r0 + chunk; r++) s += P[(size_t)r * C + col];
    part[(size_t)blockIdx.y * C + col] = s;
}

__global__ void k_colsum_comb(const float* __restrict__ part, float* __restrict__ cs,
                              int C, int splits) {
    int col = blockIdx.x * blockDim.x + threadIdx.x;
    if (col >= C) return;
    float s = 0.f;
    for (int k = 0; k < splits; k++) s += part[(size_t)k * C + col];
    cs[col] = s;
}

// ---------------- loss reductions ----------------
__global__ void k_marg(const float* __restrict__ s, int n) {
    float inv = 1.f / (float)n;
    float local = 0.f;
    for (int i = blockIdx.x * blockDim.x + threadIdx.x; i < n; i += gridDim.x * blockDim.x) {
        float d = s[i] - inv; local += d * d;
    }
    float tot = blockReduceSum(local);
    if (threadIdx.x == 0) atomicAdd(&g_acc[0], (double)tot);
}

// sail / exp / imp over the pair cost matrix
__global__ void k_pair_losses(const float* __restrict__ Mp, const float* __restrict__ u,
                              const float* __restrict__ v) {
    float sail = 0.f, expd = 0.f, impd = 0.f;
    const size_t n = (size_t)NP * NP;
    for (size_t idx = (size_t)blockIdx.x * blockDim.x + threadIdx.x; idx < n;
         idx += (size_t)gridDim.x * blockDim.x) {
        int i = (int)(idx >> 11), j = (int)(idx & 2047);
        float mval = Mp[idx];
        float cosv = mval * 0.05f;                 // Mp = 20*cos
        float z = (i == j) ? cosv * 10.f : -cosv * 10.f;
        float x = -z;                              // softplus(-z) = -log_sigmoid(z)
        float sp = (x > 0.f) ? x + log1pf(__expf(-x)) : log1pf(__expf(x));
        sail += sp;
        if (i == j) {
            expd += (1.f - cosv) * 0.5f;
            impd += mval + u[i] + v[j];
        }
    }
    float t;
    t = blockReduceSum(sail); if (threadIdx.x == 0) atomicAdd(&g_acc[1], (double)t);
    t = blockReduceSum(expd); if (threadIdx.x == 0) atomicAdd(&g_acc[2], (double)t);
    t = blockReduceSum(impd); if (threadIdx.x == 0) atomicAdd(&g_acc[3], (double)t);
}

// L_ot = sum( exp(logp_a) * (logp_a - logp_u) )
__global__ void k_ot(const float* __restrict__ Ma, const float* __restrict__ ua,
                     const float* __restrict__ va, const float* __restrict__ Mu,
                     const float* __restrict__ uu, const float* __restrict__ vu) {
    float local = 0.f;
    const size_t n = (size_t)NN * NN;
    for (size_t idx = (size_t)blockIdx.x * blockDim.x + threadIdx.x; idx < n;
         idx += (size_t)gridDim.x * blockDim.x) {
        int i = (int)(idx >> 12), j = (int)(idx & 4095);
        float lpa = Ma[idx] + ua[i] + va[j];
        float lpu = Mu[idx] + uu[i] + vu[j];
        local += __expf(lpa) * (lpa - lpu);
    }
    float tot = blockReduceSum(local);
    if (threadIdx.x == 0) atomicAdd(&g_acc[4], (double)tot);
}

__global__ void k_dot(const float* __restrict__ A, const float* __restrict__ B,
                      size_t n, int slot) {
    float local = 0.f;
    for (size_t i = (size_t)blockIdx.x * blockDim.x + threadIdx.x; i < n;
         i += (size_t)gridDim.x * blockDim.x) local += A[i] * B[i];
    float tot = blockReduceSum(local);
    if (threadIdx.x == 0) atomicAdd(&g_acc[slot], (double)tot);
}

__global__ void k_final(float* out) {
    double Npd = 2048.0;
    double cste = 4096.0 * 4096.0;
    double L = g_acc[0]
             + g_acc[1] / (Npd * Npd)
             + g_acc[2] / Npd
             + (-(g_acc[3]) / Npd - log(Npd))
             + g_acc[4]
             + (g_acc[5] + g_acc[6] - 2.0 * g_acc[7]) / cste
             + (g_acc[8] + g_acc[9] - 2.0 * g_acc[10]);
    out[0] = (float)L;
}

// ---------------- host-side helpers ----------------
static inline float* sym(const void* s) {
    void* p = nullptr;
    cudaGetSymbolAddress(&p, s);
    return (float*)p;
}

static inline void gemm(const float* A, const float* B, float* C,
                        int M, int N, int K, float alpha, bool ta, bool tb) {
    dim3 g(N / 128, M / 128), b(256);
    if (!ta && !tb)      k_gemm<false, false><<<g, b>>>(A, B, C, M, N, K, alpha);
    else if (ta && !tb)  k_gemm<true,  false><<<g, b>>>(A, B, C, M, N, K, alpha);
    else if (!ta && tb)  k_gemm<false, true ><<<g, b>>>(A, B, C, M, N, K, alpha);
    else                 k_gemm<true,  true ><<<g, b>>>(A, B, C, M, N, K, alpha);
}

static inline void run_sinkhorn(const float* M, float* u, float* v, int R, int C,
                                float* pm, float* ps) {
    float log_a = -logf((float)R), log_b = -logf((float)C);
    const int splits = 32;
    int chunk = R / splits;
    k_zero_vec<<<(C + 255) / 256, 256>>>(v, C);
    for (int it = 0; it < 10; it++) {
        k_row_lse<<<R, 256>>>(M, v, u, C, log_a);
        dim3 g(C / 256, splits);
        k_col_lse_part<<<g, 256>>>(M, u, pm, ps, C, chunk);
        k_col_lse_comb<<<(C + 255) / 256, 256>>>(pm, ps, v, C, splits, log_b);
    }
}

extern "C" void kernel_launch(void* const* d_in, const int* in_sizes, int n_in,
                              void* d_out, int out_size) {
    const float* fXp = (const float*)d_in[0];
    const float* fYp = (const float*)d_in[1];
    const float* X   = (const float*)d_in[2];
    const float* Y   = (const float*)d_in[3];
    const float* fX  = (const float*)d_in[4];
    const float* fY  = (const float*)d_in[5];
    const float* Xan = (const float*)d_in[6];
    const float* Yan = (const float*)d_in[7];
    float* out = (float*)d_out;

    float *pXa = sym(g_Xa), *pYa = sym(g_Ya);
    float *pSxx = sym(g_Sxx), *pSyy = sym(g_Syy), *pSxy = sym(g_Sxy);
    float *pfXp = sym(g_fXp), *pfYp = sym(g_fYp);
    float *pMp = sym(g_Mp), *pPp = sym(g_Pp);
    float *pfXn = sym(g_fXn), *pfYn = sym(g_fYn);
    float *pMu = sym(g_Mu), *pMa = sym(g_Ma), *pP = sym(g_P);
    float *pXS = sym(g_XS), *pYS = sym(g_YS);
    float *pXn = sym(g_Xn), *pYn = sym(g_Yn);
    float *pXu = sym(g_Xu), *pYu = sym(g_Yu);
    float *pT = sym(g_T);
    float *pCxx = sym(g_Cxx), *pCyy = sym(g_Cyy);
    float *pU1 = sym(g_U1), *pV1 = sym(g_V1);
    float *pFxx = sym(g_Fxx), *pFyy = sym(g_Fyy);
    float *pW1 = sym(g_W1), *pW2 = sym(g_W2), *pW3 = sym(g_W3);
    float *pMA = sym(g_MA);
    float *pu1 = sym(g_u1), *pv1 = sym(g_v1);
    float *pu2 = sym(g_u2), *pv2 = sym(g_v2);
    float *pu3 = sym(g_u3), *pv3 = sym(g_v3);
    float *ppm = sym(g_pm), *pps = sym(g_ps);
    float *prsp = sym(g_rsp), *pcsp = sym(g_csp);
    float *pa = sym(g_a), *pb = sym(g_b);

    k_zero_acc<<<1, 32>>>();

    // ---- anchor covariances ----
    k_rownorm<<<NN, 256>>>(Xan, pXa, DX);
    k_rownorm<<<NN, 256>>>(Yan, pYa, DY);
    const float invN = 1.0f / (float)NN;
    gemm(pXa, pXa, pSxx, DX, DX, NN, invN, true, false);
    gemm(pYa, pYa, pSyy, DY, DY, NN, invN, true, false);
    gemm(pXa, pYa, pSxy, DX, DY, NN, invN, true, false);

    // ---- cost matrices (M = cos/eps = 20*cos) ----
    k_rownorm<<<NP, 256>>>(fXp, pfXp, DF);
    k_rownorm<<<NP, 256>>>(fYp, pfYp, DF);
    gemm(pfXp, pfYp, pMp, NP, NP, DF, EPS_INV, false, true);
    k_rownorm<<<NN, 256>>>(fX, pfXn, DF);
    k_rownorm<<<NN, 256>>>(fY, pfYn, DF);
    gemm(pfXn, pfYn, pMu, NN, NN, DF, EPS_INV, false, true);

    // ---- sinkhorns (pairs + latent) ----
    run_sinkhorn(pMp, pu1, pv1, NP, NP, ppm, pps);
    run_sinkhorn(pMu, pu2, pv2, NN, NN, ppm, pps);

    // ---- plan_p: marginals + pair losses ----
    k_plan<<<2048, 256>>>(pMp, pu1, pv1, pPp, 11, 2047, (size_t)NP * NP);
    k_rowsum<<<NP, 256>>>(pPp, prsp, NP);
    {
        dim3 g(NP / 256, 32);
        k_colsum_part<<<g, 256>>>(pPp, ppm, NP, NP / 32);
        k_colsum_comb<<<(NP + 255) / 256, 256>>>(ppm, pcsp, NP, 32);
    }
    k_marg<<<(NP + 255) / 256, 256>>>(prsp, NP);
    k_marg<<<(NP + 255) / 256, 256>>>(pcsp, NP);
    k_pair_losses<<<4096, 256>>>(pMp, pu1, pv1);

    // ---- plan_u: materialize + marginals ----
    k_plan<<<4096, 256>>>(pMu, pu2, pv2, pP, 12, 4095, (size_t)NN * NN);
    k_rowsum<<<NN, 256>>>(pP, pa, NN);
    {
        dim3 g(NN / 256, 32);
        k_colsum_part<<<g, 256>>>(pP, ppm, NN, NN / 32);
        k_colsum_comb<<<(NN + 255) / 256, 256>>>(ppm, pb, NN, 32);
    }
    k_marg<<<(NN + 255) / 256, 256>>>(pa, NN);
    k_marg<<<(NN + 255) / 256, 256>>>(pb, NN);

    // ---- anchor-space plan ----
    gemm(X, pSxx, pXS, NN, DX, DX, 1.0f, false, false);
    k_metricnorm<<<NN, 256>>>(X, pXS, pXn, DX);
    gemm(Y, pSyy, pYS, NN, DY, DY, 1.0f, false, false);
    k_metricnorm<<<NN, 256>>>(Y, pYS, pYn, DY);
    gemm(pXn, pSxy, pT, NN, DY, DX, 1.0f, false, false);
    gemm(pT, pYn, pMa, NN, NN, DY, EPS_INV, false, true);
    run_sinkhorn(pMa, pu3, pv3, NN, NN, ppm, pps);
    k_ot<<<4096, 256>>>(pMa, pu3, pv3, pMu, pu2, pv2);

    // ---- L_div ----
    gemm(pXn, pXn, pCxx, DX, DX, NN, 1.0f, true, false);
    gemm(pYn, pYn, pCyy, DY, DY, NN, 1.0f, true, false);
    gemm(pCxx, pSxy, pU1, DX, DY, DX, 1.0f, false, false);
    gemm(pU1, pCyy, pV1, DX, DY, DY, 1.0f, false, false);
    k_dot<<<1024, 256>>>(pV1, pSxy, (size_t)DX * DY, 5);
    gemm(pfXn, pfXn, pFxx, DF, DF, NN, 1.0f, true, false);
    gemm(pfYn, pfYn, pFyy, DF, DF, NN, 1.0f, true, false);
    k_dot<<<256, 256>>>(pFxx, pFyy, (size_t)DF * DF, 6);
    gemm(pXn, pfXn, pW1, DX, DF, NN, 1.0f, true, false);
    gemm(pfYn, pYn, pW2, DF, DY, NN, 1.0f, true, false);
    gemm(pW1, pW2, pW3, DX, DY, DF, 1.0f, false, false);
    k_dot<<<1024, 256>>>(pW3, pSxy, (size_t)DX * DY, 7);

    // ---- L_gw (factored; Kx/Ky never materialized) ----
    k_rownorm<<<NN, 256>>>(X, pXu, DX);
    k_rownorm<<<NN, 256>>>(Y, pYu, DY);
    // aKx^2a = || Xu^T diag(a) Xu ||_F^2
    k_rowscale<<<4096, 256>>>(pXu, pa, pXS, DX, (size_t)NN * DX);
    gemm(pXu, pXS, pMA, DX, DX, NN, 1.0f, true, false);
    k_dot<<<1024, 256>>>(pMA, pMA, (size_t)DX * DX, 8);
    // bKy^2b = || Yu^T diag(b) Yu ||_F^2
    k_rowscale<<<4096, 256>>>(pYu, pb, pYS, DY, (size_t)NN * DY);
    gemm(pYu, pYS, pMA, DY, DY, NN, 1.0f, true, false);
    k_dot<<<1024, 256>>>(pMA, pMA, (size_t)DY * DY, 9);
    // cross term = || Xu^T P Yu ||_F^2
    gemm(pP, pYu, pT, NN, DY, NN, 1.0f, false, false);   // PY (reuse g_T)
    gemm(pXu, pT, pMA, DX, DY, NN, 1.0f, true, false);   // G  (reuse g_MA)
    k_dot<<<1024, 256>>>(pMA, pMA, (size_t)DX * DY, 10);

    // ---- combine ----
    k_final<<<1, 1>>>(out);
}

// round 6
// speedup vs baseline: 2.6631x; 2.6631x over previous
#include <cuda_runtime.h>
#include <math.h>

// ---------------- problem constants ----------------
#define NP 2048        // pairs
#define NN 4096        // X/Y rows
#define DF 256         // latent dim
#define DX 768         // X dim
#define DY 512         // Y dim
#define CLAMPF 1e-8f
#define EPS_INV 20.0f  // 1/0.05

// ---------------- static device scratch ----------------
__device__ alignas(16) float g_Xa[NN*DX];
__device__ alignas(16) float g_Ya[NN*DY];
__device__ alignas(16) float g_Sxx[DX*DX];
__device__ alignas(16) float g_Syy[DY*DY];
__device__ alignas(16) float g_Sxy[DX*DY];
__device__ alignas(16) float g_fXp[NP*DF];
__device__ alignas(16) float g_fYp[NP*DF];
__device__ alignas(16) float g_Mp[(size_t)NP*NP];
__device__ alignas(16) float g_fXn[NN*DF];
__device__ alignas(16) float g_fYn[NN*DF];
__device__ alignas(16) float g_Mu[(size_t)NN*NN];
__device__ alignas(16) float g_Ma[(size_t)NN*NN];
__device__ alignas(16) float g_P [(size_t)NN*NN];
__device__ alignas(16) float g_XS[NN*DX];   // X@Sxx, later reused as diag(a)*Xu
__device__ alignas(16) float g_YS[NN*DY];   // Y@Syy, later reused as diag(b)*Yu
__device__ alignas(16) float g_Xn[NN*DX];
__device__ alignas(16) float g_Yn[NN*DY];
__device__ alignas(16) float g_Xu[NN*DX];
__device__ alignas(16) float g_Yu[NN*DY];
__device__ alignas(16) float g_T [NN*DY];   // Xn@Sxy, later reused as P@Yu
__device__ alignas(16) float g_Cxx[DX*DX];
__device__ alignas(16) float g_Cyy[DY*DY];
__device__ alignas(16) float g_U1[DX*DY];
__device__ alignas(16) float g_V1[DX*DY];
__device__ alignas(16) float g_Fxx[DF*DF];
__device__ alignas(16) float g_Fyy[DF*DF];
__device__ alignas(16) float g_W1[DX*DF];
__device__ alignas(16) float g_W2[DF*DY];
__device__ alignas(16) float g_W3[DX*DY];
__device__ alignas(16) float g_MA[DX*DX];   // MAx, then MAy, then G (sequential reuse)
__device__ alignas(16) float g_skw[8*DX*DX];// split-K workspace (max: S=8 of 768x768)
__device__ float g_u1[NP], g_v1[NP];      // sinkhorn pairs
__device__ float g_u2[NN], g_v2[NN];      // sinkhorn latent
__device__ float g_u3[NN], g_v3[NN];      // sinkhorn anchor
__device__ float g_pm[64*NN], g_ps[64*NN];// col-LSE partials
__device__ float g_rsp[NP], g_csp[NP];    // plan_p marginals
__device__ float g_a[NN], g_b[NN];        // plan_u marginals
__device__ double g_acc[16];

// acc slots:
// 0: L_marg  1: sail-sum  2: exp-diag-sum  3: imp-diag-logp-sum
// 4: L_ot    5: norm1     6: norm2         7: dot
// 8: frob(MAx) 9: frob(MAy) 10: frob(G)

// ---------------- reduction helper ----------------
__device__ __forceinline__ float blockReduceSum(float v) {
    __shared__ float sh[32];
    __syncthreads();                       // protect prior use of sh
    int lane = threadIdx.x & 31, wid = threadIdx.x >> 5;
    #pragma unroll
    for (int o = 16; o > 0; o >>= 1) v += __shfl_down_sync(0xffffffffu, v, o);
    if (lane == 0) sh[wid] = v;
    __syncthreads();
    int nw = blockDim.x >> 5;
    v = (threadIdx.x < nw) ? sh[threadIdx.x] : 0.f;
    if (wid == 0) {
        #pragma unroll
        for (int o = 16; o > 0; o >>= 1) v += __shfl_down_sync(0xffffffffu, v, o);
    }
    return v;  // valid on thread 0
}

// ---------------- elementwise / norms ----------------
__global__ void k_zero_acc() { if (threadIdx.x < 16) g_acc[threadIdx.x] = 0.0; }

__global__ void k_zero_vec(float* v, int n) {
    int i = blockIdx.x * blockDim.x + threadIdx.x;
    if (i < n) v[i] = 0.f;
}

__global__ void k_rownorm(const float* __restrict__ in, float* __restrict__ out, int cols) {
    int row = blockIdx.x;
    const float* r = in + (size_t)row * cols;
    float ss = 0.f;
    for (int c = threadIdx.x; c < cols; c += blockDim.x) { float x = r[c]; ss += x * x; }
    float tot = blockReduceSum(ss);
    __shared__ float sInv;
    if (threadIdx.x == 0) sInv = 1.f / fmaxf(sqrtf(tot), CLAMPF);
    __syncthreads();
    float inv = sInv;
    float* o = out + (size_t)row * cols;
    for (int c = threadIdx.x; c < cols; c += blockDim.x) o[c] = r[c] * inv;
}

// Xn = X / clamp(sqrt(rowdot(X, XS)))
__global__ void k_metricnorm(const float* __restrict__ X, const float* __restrict__ XS,
                             float* __restrict__ Xn, int cols) {
    int row = blockIdx.x;
    const float* r  = X  + (size_t)row * cols;
    const float* rs = XS + (size_t)row * cols;
    float ss = 0.f;
    for (int c = threadIdx.x; c < cols; c += blockDim.x) ss += r[c] * rs[c];
    float tot = blockReduceSum(ss);
    __shared__ float sInv;
    if (threadIdx.x == 0) sInv = 1.f / fmaxf(sqrtf(tot), CLAMPF);
    __syncthreads();
    float inv = sInv;
    float* o = Xn + (size_t)row * cols;
    for (int c = threadIdx.x; c < cols; c += blockDim.x) o[c] = r[c] * inv;
}

__global__ void k_rowscale(const float* __restrict__ in, const float* __restrict__ s,
                           float* __restrict__ out, int C, size_t n) {
    for (size_t idx = (size_t)blockIdx.x * blockDim.x + threadIdx.x; idx < n;
         idx += (size_t)gridDim.x * blockDim.x) {
        int i = (int)(idx / C);
        out[idx] = in[idx] * s[i];
    }
}

// ---------------- GEMM: C = alpha * op(A) @ op(B) ----------------
// logical A is MxK: TA ? stored KxM : stored MxK (row-major)
// logical B is KxN: TB ? stored NxK : stored KxN
// M,N multiples of 128; K multiple of 8. gridDim.z = split-K factor;
// block z handles k in [z*Kc, (z+1)*Kc) and writes slice z of C (M*N each).
// Double-buffered SMEM, register-staged prefetch, 1 sync per k-tile.
template<bool TA, bool TB>
__global__ void __launch_bounds__(256, 2)
k_gemm(const float* __restrict__ A, const float* __restrict__ B,
       float* __restrict__ C, int M, int N, int K, int Kc, float alpha) {
    __shared__ alignas(16) float As[2][8][132];
    __shared__ alignas(16) float Bs[2][8][132];
    int bm = blockIdx.y * 128, bn = blockIdx.x * 128;
    int kb = blockIdx.z * Kc;
    C += (size_t)blockIdx.z * M * N;
    int tid = threadIdx.x;
    int tx = tid & 15, ty = tid >> 4;   // 16x16 threads

    float acc[8][8];
    #pragma unroll
    for (int i = 0; i < 8; i++)
        #pragma unroll
        for (int j = 0; j < 8; j++) acc[i][j] = 0.f;

    float sA[4];     // staging (scalar path)
    float4 sA4;      // staging (vector path)
    float sB[4];
    float4 sB4;

    auto loadA = [&](int k0) {
        if (!TA) {
            int k = tid & 7, m0 = tid >> 3;
            #pragma unroll
            for (int r = 0; r < 4; r++)
                sA[r] = A[(size_t)(bm + m0 + r * 32) * K + (k0 + k)];
        } else {
            int k = tid >> 5, m4 = (tid & 31) * 4;
            sA4 = *reinterpret_cast<const float4*>(&A[(size_t)(k0 + k) * M + bm + m4]);
        }
    };
    auto storeA = [&](int b) {
        if (!TA) {
            int k = tid & 7, m0 = tid >> 3;
            #pragma unroll
            for (int r = 0; r < 4; r++) As[b][k][m0 + r * 32] = sA[r];
        } else {
            int k = tid >> 5, m4 = (tid & 31) * 4;
            *reinterpret_cast<float4*>(&As[b][k][m4]) = sA4;
        }
    };
    auto loadB = [&](int k0) {
        if (!TB) {
            int k = tid >> 5, n4 = (tid & 31) * 4;
            sB4 = *reinterpret_cast<const float4*>(&B[(size_t)(k0 + k) * N + bn + n4]);
        } else {
            int k = tid & 7, n0 = tid >> 3;
            #pragma unroll
            for (int r = 0; r < 4; r++)
                sB[r] = B[(size_t)(bn + n0 + r * 32) * K + (k0 + k)];
        }
    };
    auto storeB = [&](int b) {
        if (!TB) {
            int k = tid >> 5, n4 = (tid & 31) * 4;
            *reinterpret_cast<float4*>(&Bs[b][k][n4]) = sB4;
        } else {
            int k = tid & 7, n0 = tid >> 3;
            #pragma unroll
            for (int r = 0; r < 4; r++) Bs[b][k][n0 + r * 32] = sB[r];
        }
    };

    loadA(kb); loadB(kb);
    storeA(0); storeB(0);
    __syncthreads();
    int buf = 0;
    for (int k0 = kb; k0 < kb + Kc; k0 += 8) {
        bool more = (k0 + 8 < kb + Kc);
        if (more) { loadA(k0 + 8); loadB(k0 + 8); }
        #pragma unroll
        for (int k = 0; k < 8; k++) {
            const float4* ap = reinterpret_cast<const float4*>(&As[buf][k][ty * 8]);
            const float4* bp = reinterpret_cast<const float4*>(&Bs[buf][k][tx * 8]);
            float4 a0 = ap[0], a1 = ap[1];
            float4 b0 = bp[0], b1 = bp[1];
            float ra[8] = {a0.x, a0.y, a0.z, a0.w, a1.x, a1.y, a1.z, a1.w};
            float rb[8] = {b0.x, b0.y, b0.z, b0.w, b1.x, b1.y, b1.z, b1.w};
            #pragma unroll
            for (int i = 0; i < 8; i++)
                #pragma unroll
                for (int j = 0; j < 8; j++) acc[i][j] = fmaf(ra[i], rb[j], acc[i][j]);
        }
        if (more) {
            storeA(buf ^ 1); storeB(buf ^ 1);
            __syncthreads();
            buf ^= 1;
        }
    }
    #pragma unroll
    for (int i = 0; i < 8; i++) {
        int gm = bm + ty * 8 + i;
        float* cp = &C[(size_t)gm * N + bn + tx * 8];
        float4 o0 = make_float4(alpha * acc[i][0], alpha * acc[i][1],
                                alpha * acc[i][2], alpha * acc[i][3]);
        float4 o1 = make_float4(alpha * acc[i][4], alpha * acc[i][5],
                                alpha * acc[i][6], alpha * acc[i][7]);
        reinterpret_cast<float4*>(cp)[0] = o0;
        reinterpret_cast<float4*>(cp)[1] = o1;
    }
}

// Sum S slices of the split-K workspace into C (deterministic order).
__global__ void k_sk_reduce(const float* __restrict__ W, float* __restrict__ C,
                            size_t mn, int S) {
    for (size_t i = (size_t)blockIdx.x * blockDim.x + threadIdx.x; i < mn;
         i += (size_t)gridDim.x * blockDim.x) {
        float s = 0.f;
        for (int k = 0; k < S; k++) s += W[(size_t)k * mn + i];
        C[i] = s;
    }
}

// ---------------- Sinkhorn (log-domain, online LSE) ----------------
__global__ void k_row_lse(const float* __restrict__ M, const float* __restrict__ v,
                          float* __restrict__ u, int C, float log_a) {
    int row = blockIdx.x;
    const float* r = M + (size_t)row * C;
    float m = -1e30f, s = 0.f;
    for (int c = threadIdx.x; c < C; c += blockDim.x) {
        float x = r[c] + v[c];
        if (x > m) { s = s * __expf(m - x) + 1.f; m = x; }
        else s += __expf(x - m);
    }
    __shared__ float shm[256], shs[256];
    shm[threadIdx.x] = m; shs[threadIdx.x] = s;
    __syncthreads();
    for (int off = blockDim.x >> 1; off > 0; off >>= 1) {
        if (threadIdx.x < off) {
            float m1 = shm[threadIdx.x], s1 = shs[threadIdx.x];
            float m2 = shm[threadIdx.x + off], s2 = shs[threadIdx.x + off];
            float mm = fmaxf(m1, m2);
            shm[threadIdx.x] = mm;
            shs[threadIdx.x] = s1 * __expf(m1 - mm) + s2 * __expf(m2 - mm);
        }
        __syncthreads();
    }
    if (threadIdx.x == 0) u[row] = log_a - (shm[0] + logf(shs[0]));
}

__global__ void k_col_lse_part(const float* __restrict__ M, const float* __restrict__ u,
                               float* __restrict__ pm, float* __restrict__ ps,
                               int C, int chunk) {
    int col = blockIdx.x * blockDim.x + threadIdx.x;
    int r0 = blockIdx.y * chunk;
    float m = -1e30f, s = 0.f;
    for (int r = r0; r < r0 + chunk; r++) {
        float x = M[(size_t)r * C + col] + u[r];
        if (x > m) { s = s * __expf(m - x) + 1.f; m = x; }
        else s += __expf(x - m);
    }
    pm[(size_t)blockIdx.y * C + col] = m;
    ps[(size_t)blockIdx.y * C + col] = s;
}

__global__ void k_col_lse_comb(const float* __restrict__ pm, const float* __restrict__ ps,
                               float* __restrict__ v, int C, int splits, float log_b) {
    int col = blockIdx.x * blockDim.x + threadIdx.x;
    if (col >= C) return;
    float m = -1e30f, s = 0.f;
    for (int k = 0; k < splits; k++) {
        float m2 = pm[(size_t)k * C + col], s2 = ps[(size_t)k * C + col];
        float mm = fmaxf(m, m2);
        s = s * __expf(m - mm) + s2 * __expf(m2 - mm);
        m = mm;
    }
    v[col] = log_b - (m + logf(s));
}

// P = exp(M + u_i + v_j); shift/mask for pow2 column count
__global__ void k_plan(const float* __restrict__ M, const float* __restrict__ u,
                       const float* __restrict__ v, float* __restrict__ P,
                       int shift, int mask, size_t n) {
    for (size_t idx = (size_t)blockIdx.x * blockDim.x + threadIdx.x; idx < n;
         idx += (size_t)gridDim.x * blockDim.x) {
        int i = (int)(idx >> shift), j = (int)(idx & mask);
        P[idx] = __expf(M[idx] + u[i] + v[j]);
    }
}

__global__ void k_rowsum(const float* __restrict__ P, float* __restrict__ rs, int C) {
    int row = blockIdx.x;
    const float* r = P + (size_t)row * C;
    float s = 0.f;
    for (int c = threadIdx.x; c < C; c += blockDim.x) s += r[c];
    float tot = blockReduceSum(s);
    if (threadIdx.x == 0) rs[row] = tot;
}

__global__ void k_colsum_part(const float* __restrict__ P, float* __restrict__ part,
                              int C, int chunk) {
    int col = blockIdx.x * blockDim.x + threadIdx.x;
    int r0 = blockIdx.y * chunk;
    float s = 0.f;
    for (int r = r0; r < r0 + chunk; r++) s += P[(size_t)r * C + col];
    part[(size_t)blockIdx.y * C + col] = s;
}

__global__ void k_colsum_comb(const float* __restrict__ part, float* __restrict__ cs,
                              int C, int splits) {
    int col = blockIdx.x * blockDim.x + threadIdx.x;
    if (col >= C) return;
    float s = 0.f;
    for (int k = 0; k < splits; k++) s += part[(size_t)k * C + col];
    cs[col] = s;
}

// row sums of exp(M + u_i + v_j), no plan materialization (pair plan)
__global__ void k_exp_rowsum(const float* __restrict__ M, const float* __restrict__ u,
                             const float* __restrict__ v, float* __restrict__ rs, int C) {
    int row = blockIdx.x;
    const float* r = M + (size_t)row * C;
    float uu = u[row];
    float s = 0.f;
    for (int c = threadIdx.x; c < C; c += blockDim.x) s += __expf(r[c] + uu + v[c]);
    float tot = blockReduceSum(s);
    if (threadIdx.x == 0) rs[row] = tot;
}

__global__ void k_exp_colsum_part(const float* __restrict__ M, const float* __restrict__ u,
                                  const float* __restrict__ v, float* __restrict__ part,
                                  int C, int chunk) {
    int col = blockIdx.x * blockDim.x + threadIdx.x;
    int r0 = blockIdx.y * chunk;
    float vv = v[col];
    float s = 0.f;
    for (int r = r0; r < r0 + chunk; r++) s += __expf(M[(size_t)r * C + col] + u[r] + vv);
    part[(size_t)blockIdx.y * C + col] = s;
}

// ---------------- loss reductions ----------------
__global__ void k_marg(const float* __restrict__ s, int n) {
    float inv = 1.f / (float)n;
    float local = 0.f;
    for (int i = blockIdx.x * blockDim.x + threadIdx.x; i < n; i += gridDim.x * blockDim.x) {
        float d = s[i] - inv; local += d * d;
    }
    float tot = blockReduceSum(local);
    if (threadIdx.x == 0) atomicAdd(&g_acc[0], (double)tot);
}

// sail / exp / imp over the pair cost matrix
__global__ void k_pair_losses(const float* __restrict__ Mp, const float* __restrict__ u,
                              const float* __restrict__ v) {
    float sail = 0.f, expd = 0.f, impd = 0.f;
    const size_t n = (size_t)NP * NP;
    for (size_t idx = (size_t)blockIdx.x * blockDim.x + threadIdx.x; idx < n;
         idx += (size_t)gridDim.x * blockDim.x) {
        int i = (int)(idx >> 11), j = (int)(idx & 2047);
        float mval = Mp[idx];
        float cosv = mval * 0.05f;                 // Mp = 20*cos
        float z = (i == j) ? cosv * 10.f : -cosv * 10.f;
        float x = -z;                              // softplus(-z) = -log_sigmoid(z)
        float sp = (x > 0.f) ? x + log1pf(__expf(-x)) : log1pf(__expf(x));
        sail += sp;
        if (i == j) {
            expd += (1.f - cosv) * 0.5f;
            impd += mval + u[i] + v[j];
        }
    }
    float t;
    t = blockReduceSum(sail); if (threadIdx.x == 0) atomicAdd(&g_acc[1], (double)t);
    t = blockReduceSum(expd); if (threadIdx.x == 0) atomicAdd(&g_acc[2], (double)t);
    t = blockReduceSum(impd); if (threadIdx.x == 0) atomicAdd(&g_acc[3], (double)t);
}

// L_ot = sum( exp(logp_a) * (logp_a - logp_u) )
__global__ void k_ot(const float* __restrict__ Ma, const float* __restrict__ ua,
                     const float* __restrict__ va, const float* __restrict__ Mu,
                     const float* __restrict__ uu, const float* __restrict__ vu) {
    float local = 0.f;
    const size_t n = (size_t)NN * NN;
    for (size_t idx = (size_t)blockIdx.x * blockDim.x + threadIdx.x; idx < n;
         idx += (size_t)gridDim.x * blockDim.x) {
        int i = (int)(idx >> 12), j = (int)(idx & 4095);
        float lpa = Ma[idx] + ua[i] + va[j];
        float lpu = Mu[idx] + uu[i] + vu[j];
        local += __expf(lpa) * (lpa - lpu);
    }
    float tot = blockReduceSum(local);
    if (threadIdx.x == 0) atomicAdd(&g_acc[4], (double)tot);
}

__global__ void k_dot(const float* __restrict__ A, const float* __restrict__ B,
                      size_t n, int slot) {
    float local = 0.f;
    for (size_t i = (size_t)blockIdx.x * blockDim.x + threadIdx.x; i < n;
         i += (size_t)gridDim.x * blockDim.x) local += A[i] * B[i];
    float tot = blockReduceSum(local);
    if (threadIdx.x == 0) atomicAdd(&g_acc[slot], (double)tot);
}

__global__ void k_final(float* out) {
    double Npd = 2048.0;
    double cste = 4096.0 * 4096.0;
    double L = g_acc[0]
             + g_acc[1] / (Npd * Npd)
             + g_acc[2] / Npd
             + (-(g_acc[3]) / Npd - log(Npd))
             + g_acc[4]
             + (g_acc[5] + g_acc[6] - 2.0 * g_acc[7]) / cste
             + (g_acc[8] + g_acc[9] - 2.0 * g_acc[10]);
    out[0] = (float)L;
}

// ---------------- host-side helpers ----------------
static inline float* sym(const void* s) {
    void* p = nullptr;
    cudaGetSymbolAddress(&p, s);
    return (float*)p;
}

// S = split-K factor (K % S == 0 and (K/S) % 8 == 0 required).
static inline void gemm(const float* A, const float* B, float* C,
                        int M, int N, int K, float alpha, bool ta, bool tb, int S = 1) {
    float* out = C;
    if (S > 1) out = sym(g_skw);
    int Kc = K / S;
    dim3 g(N / 128, M / 128, S), b(256);
    if (!ta && !tb)      k_gemm<false, false><<<g, b>>>(A, B, out, M, N, K, Kc, alpha);
    else if (ta && !tb)  k_gemm<true,  false><<<g, b>>>(A, B, out, M, N, K, Kc, alpha);
    else if (!ta && tb)  k_gemm<false, true ><<<g, b>>>(A, B, out, M, N, K, Kc, alpha);
    else                 k_gemm<true,  true ><<<g, b>>>(A, B, out, M, N, K, Kc, alpha);
    if (S > 1) {
        size_t mn = (size_t)M * N;
        int blocks = (int)((mn + 255) / 256);
        if (blocks > 1024) blocks = 1024;
        k_sk_reduce<<<blocks, 256>>>(out, C, mn, S);
    }
}

static inline void run_sinkhorn(const float* M, float* u, float* v, int R, int C,
                                float* pm, float* ps) {
    float log_a = -logf((float)R), log_b = -logf((float)C);
    const int splits = 32;
    int chunk = R / splits;
    k_zero_vec<<<(C + 255) / 256, 256>>>(v, C);
    for (int it = 0; it < 10; it++) {
        k_row_lse<<<R, 256>>>(M, v, u, C, log_a);
        dim3 g(C / 256, splits);
        k_col_lse_part<<<g, 256>>>(M, u, pm, ps, C, chunk);
        k_col_lse_comb<<<(C + 255) / 256, 256>>>(pm, ps, v, C, splits, log_b);
    }
}

extern "C" void kernel_launch(void* const* d_in, const int* in_sizes, int n_in,
                              void* d_out, int out_size) {
    const float* fXp = (const float*)d_in[0];
    const float* fYp = (const float*)d_in[1];
    const float* X   = (const float*)d_in[2];
    const float* Y   = (const float*)d_in[3];
    const float* fX  = (const float*)d_in[4];
    const float* fY  = (const float*)d_in[5];
    const float* Xan = (const float*)d_in[6];
    const float* Yan = (const float*)d_in[7];
    float* out = (float*)d_out;

    float *pXa = sym(g_Xa), *pYa = sym(g_Ya);
    float *pSxx = sym(g_Sxx), *pSyy = sym(g_Syy), *pSxy = sym(g_Sxy);
    float *pfXp = sym(g_fXp), *pfYp = sym(g_fYp);
    float *pMp = sym(g_Mp);
    float *pfXn = sym(g_fXn), *pfYn = sym(g_fYn);
    float *pMu = sym(g_Mu), *pMa = sym(g_Ma), *pP = sym(g_P);
    float *pXS = sym(g_XS), *pYS = sym(g_YS);
    float *pXn = sym(g_Xn), *pYn = sym(g_Yn);
    float *pXu = sym(g_Xu), *pYu = sym(g_Yu);
    float *pT = sym(g_T);
    float *pCxx = sym(g_Cxx), *pCyy = sym(g_Cyy);
    float *pU1 = sym(g_U1), *pV1 = sym(g_V1);
    float *pFxx = sym(g_Fxx), *pFyy = sym(g_Fyy);
    float *pW1 = sym(g_W1), *pW2 = sym(g_W2), *pW3 = sym(g_W3);
    float *pMA = sym(g_MA);
    float *pu1 = sym(g_u1), *pv1 = sym(g_v1);
    float *pu2 = sym(g_u2), *pv2 = sym(g_v2);
    float *pu3 = sym(g_u3), *pv3 = sym(g_v3);
    float *ppm = sym(g_pm), *pps = sym(g_ps);
    float *prsp = sym(g_rsp), *pcsp = sym(g_csp);
    float *pa = sym(g_a), *pb = sym(g_b);

    k_zero_acc<<<1, 32>>>();

    // ---- anchor covariances (split-K: grids were 36/16/24) ----
    k_rownorm<<<NN, 256>>>(Xan, pXa, DX);
    k_rownorm<<<NN, 256>>>(Yan, pYa, DY);
    const float invN = 1.0f / (float)NN;
    gemm(pXa, pXa, pSxx, DX, DX, NN, invN, true, false, 8);
    gemm(pYa, pYa, pSyy, DY, DY, NN, invN, true, false, 8);
    gemm(pXa, pYa, pSxy, DX, DY, NN, invN, true, false, 8);

    // ---- cost matrices (M = cos/eps = 20*cos) ----
    k_rownorm<<<NP, 256>>>(fXp, pfXp, DF);
    k_rownorm<<<NP, 256>>>(fYp, pfYp, DF);
    gemm(pfXp, pfYp, pMp, NP, NP, DF, EPS_INV, false, true);
    k_rownorm<<<NN, 256>>>(fX, pfXn, DF);
    k_rownorm<<<NN, 256>>>(fY, pfYn, DF);
    gemm(pfXn, pfYn, pMu, NN, NN, DF, EPS_INV, false, true);

    // ---- sinkhorns (pairs + latent) ----
    run_sinkhorn(pMp, pu1, pv1, NP, NP, ppm, pps);
    run_sinkhorn(pMu, pu2, pv2, NN, NN, ppm, pps);

    // ---- plan_p marginals (exp fused, no plan materialization) + pair losses ----
    k_exp_rowsum<<<NP, 256>>>(pMp, pu1, pv1, prsp, NP);
    {
        dim3 g(NP / 256, 32);
        k_exp_colsum_part<<<g, 256>>>(pMp, pu1, pv1, ppm, NP, NP / 32);
        k_colsum_comb<<<(NP + 255) / 256, 256>>>(ppm, pcsp, NP, 32);
    }
    k_marg<<<(NP + 255) / 256, 256>>>(prsp, NP);
    k_marg<<<(NP + 255) / 256, 256>>>(pcsp, NP);
    k_pair_losses<<<4096, 256>>>(pMp, pu1, pv1);

    // ---- plan_u: materialize (needed for P@Yu) + marginals ----
    k_plan<<<4096, 256>>>(pMu, pu2, pv2, pP, 12, 4095, (size_t)NN * NN);
    k_rowsum<<<NN, 256>>>(pP, pa, NN);
    {
        dim3 g(NN / 256, 32);
        k_colsum_part<<<g, 256>>>(pP, ppm, NN, NN / 32);
        k_colsum_comb<<<(NN + 255) / 256, 256>>>(ppm, pb, NN, 32);
    }
    k_marg<<<(NN + 255) / 256, 256>>>(pa, NN);
    k_marg<<<(NN + 255) / 256, 256>>>(pb, NN);

    // ---- anchor-space plan ----
    gemm(X, pSxx, pXS, NN, DX, DX, 1.0f, false, false);           // grid 192
    k_metricnorm<<<NN, 256>>>(X, pXS, pXn, DX);
    gemm(Y, pSyy, pYS, NN, DY, DY, 1.0f, false, false, 2);        // 128 -> 256
    k_metricnorm<<<NN, 256>>>(Y, pYS, pYn, DY);
    gemm(pXn, pSxy, pT, NN, DY, DX, 1.0f, false, false, 2);       // 128 -> 256
    gemm(pT, pYn, pMa, NN, NN, DY, EPS_INV, false, true);         // grid 1024
    run_sinkhorn(pMa, pu3, pv3, NN, NN, ppm, pps);
    k_ot<<<4096, 256>>>(pMa, pu3, pv3, pMu, pu2, pv2);

    // ---- L_div ----
    gemm(pXn, pXn, pCxx, DX, DX, NN, 1.0f, true, false, 8);
    gemm(pYn, pYn, pCyy, DY, DY, NN, 1.0f, true, false, 8);
    gemm(pCxx, pSxy, pU1, DX, DY, DX, 1.0f, false, false, 6);     // Kc=128
    gemm(pU1, pCyy, pV1, DX, DY, DY, 1.0f, false, false, 8);      // Kc=64
    k_dot<<<1024, 256>>>(pV1, pSxy, (size_t)DX * DY, 5);
    gemm(pfXn, pfXn, pFxx, DF, DF, NN, 1.0f, true, false, 32);    // 4 -> 128
    gemm(pfYn, pfYn, pFyy, DF, DF, NN, 1.0f, true, false, 32);
    k_dot<<<256, 256>>>(pFxx, pFyy, (size_t)DF * DF, 6);
    gemm(pXn, pfXn, pW1, DX, DF, NN, 1.0f, true, false, 16);      // 12 -> 192
    gemm(pfYn, pYn, pW2, DF, DY, NN, 1.0f, true, false, 16);      // 8 -> 128
    gemm(pW1, pW2, pW3, DX, DY, DF, 1.0f, false, false, 8);       // Kc=32
    k_dot<<<1024, 256>>>(pW3, pSxy, (size_t)DX * DY, 7);

    // ---- L_gw (factored; Kx/Ky never materialized) ----
    k_rownorm<<<NN, 256>>>(X, pXu, DX);
    k_rownorm<<<NN, 256>>>(Y, pYu, DY);
    // aKx^2a = || Xu^T diag(a) Xu ||_F^2
    k_rowscale<<<4096, 256>>>(pXu, pa, pXS, DX, (size_t)NN * DX);
    gemm(pXu, pXS, pMA, DX, DX, NN, 1.0f, true, false, 8);
    k_dot<<<1024, 256>>>(pMA, pMA, (size_t)DX * DX, 8);
    // bKy^2b = || Yu^T diag(b) Yu ||_F^2
    k_rowscale<<<4096, 256>>>(pYu, pb, pYS, DY, (size_t)NN * DY);
    gemm(pYu, pYS, pMA, DY, DY, NN, 1.0f, true, false, 8);
    k_dot<<<1024, 256>>>(pMA, pMA, (size_t)DY * DY, 9);
    // cross term = || Xu^T P Yu ||_F^2
    gemm(pP, pYu, pT, NN, DY, NN, 1.0f, false, false, 2);         // 128 -> 256
    gemm(pXu, pT, pMA, DX, DY, NN, 1.0f, true, false, 8);         // 24 -> 192
    k_dot<<<1024, 256>>>(pMA, pMA, (size_t)DX * DY, 10);

    // ---- combine ----
    k_final<<<1, 1>>>(out);
}

// round 9
// speedup vs baseline: 3.2911x; 1.2358x over previous
#include <cuda_runtime.h>
#include <math.h>

// ---------------- problem constants ----------------
#define NP 2048        // pairs
#define NN 4096        // X/Y rows
#define DF 256         // latent dim
#define DX 768         // X dim
#define DY 512         // Y dim
#define CLAMPF 1e-8f
#define EPS_INV 20.0f  // 1/0.05

// ---------------- static device scratch ----------------
__device__ alignas(16) float g_Xa[NN*DX];
__device__ alignas(16) float g_Ya[NN*DY];
__device__ alignas(16) float g_Sxx[DX*DX];
__device__ alignas(16) float g_Syy[DY*DY];
__device__ alignas(16) float g_Sxy[DX*DY];
__device__ alignas(16) float g_fXp[NP*DF];
__device__ alignas(16) float g_fYp[NP*DF];
__device__ alignas(16) float g_Mp[(size_t)NP*NP];
__device__ alignas(16) float g_fXn[NN*DF];
__device__ alignas(16) float g_fYn[NN*DF];
__device__ alignas(16) float g_Mu[(size_t)NN*NN];
__device__ alignas(16) float g_Ma[(size_t)NN*NN];
__device__ alignas(16) float g_P [(size_t)NN*NN];
__device__ alignas(16) float g_XS[NN*DX];   // X@Sxx, later reused as diag(a)*Xu
__device__ alignas(16) float g_YS[NN*DY];   // Y@Syy, later reused as diag(b)*Yu
__device__ alignas(16) float g_Xn[NN*DX];
__device__ alignas(16) float g_Yn[NN*DY];
__device__ alignas(16) float g_Xu[NN*DX];
__device__ alignas(16) float g_Yu[NN*DY];
__device__ alignas(16) float g_T [NN*DY];   // Xn@Sxy, later reused as P@Yu
__device__ alignas(16) float g_Cxx[DX*DX];
__device__ alignas(16) float g_Cyy[DY*DY];
__device__ alignas(16) float g_U1[DX*DY];
__device__ alignas(16) float g_V1[DX*DY];
__device__ alignas(16) float g_Fxx[DF*DF];
__device__ alignas(16) float g_Fyy[DF*DF];
__device__ alignas(16) float g_W1[DX*DF];
__device__ alignas(16) float g_W2[DF*DY];
__device__ alignas(16) float g_W3[DX*DY];
__device__ alignas(16) float g_MA[DX*DX];   // MAx, then MAy, then G (sequential reuse)
__device__ alignas(16) float g_skw[8*DX*DX];// split-K workspace (max: S=8 of 768x768)
__device__ alignas(16) float g_u1[NP];
__device__ alignas(16) float g_v1[NP];      // sinkhorn pairs
__device__ alignas(16) float g_u2[NN];
__device__ alignas(16) float g_v2[NN];      // sinkhorn latent
__device__ alignas(16) float g_u3[NN];
__device__ alignas(16) float g_v3[NN];      // sinkhorn anchor
__device__ alignas(16) float g_pm[64*NN];
__device__ alignas(16) float g_ps[64*NN];   // partial arrays
__device__ alignas(16) float g_rsp[NP];
__device__ alignas(16) float g_csp[NP];     // plan_p marginals
__device__ alignas(16) float g_a[NN];
__device__ alignas(16) float g_b[NN];       // plan_u marginals
__device__ double g_acc[16];

// acc slots:
// 0: L_marg  1: sail-sum  2: exp-diag-sum  3: imp-diag-logp-sum
// 4: L_ot    5: norm1     6: norm2         7: dot
// 8: frob(MAx) 9: frob(MAy) 10: frob(G)

// ---------------- packed dual-fp32 FMA (sm_103a) ----------------
__device__ __forceinline__ float2 ffma2(float2 a, float2 b, float2 c) {
    float2 d;
    asm("{\n\t"
        ".reg .b64 ra, rb, rc, rd;\n\t"
        "mov.b64 ra, {%2, %3};\n\t"
        "mov.b64 rb, {%4, %5};\n\t"
        "mov.b64 rc, {%6, %7};\n\t"
        "fma.rn.f32x2 rd, ra, rb, rc;\n\t"
        "mov.b64 {%0, %1}, rd;\n\t"
        "}"
        : "=f"(d.x), "=f"(d.y)
        : "f"(a.x), "f"(a.y), "f"(b.x), "f"(b.y), "f"(c.x), "f"(c.y));
    return d;
}

// ---------------- reduction helper ----------------
__device__ __forceinline__ float blockReduceSum(float v) {
    __shared__ float sh[32];
    __syncthreads();                       // protect prior use of sh
    int lane = threadIdx.x & 31, wid = threadIdx.x >> 5;
    #pragma unroll
    for (int o = 16; o > 0; o >>= 1) v += __shfl_down_sync(0xffffffffu, v, o);
    if (lane == 0) sh[wid] = v;
    __syncthreads();
    int nw = blockDim.x >> 5;
    v = (threadIdx.x < nw) ? sh[threadIdx.x] : 0.f;
    if (wid == 0) {
        #pragma unroll
        for (int o = 16; o > 0; o >>= 1) v += __shfl_down_sync(0xffffffffu, v, o);
    }
    return v;  // valid on thread 0
}

// ---------------- elementwise / norms ----------------
__global__ void k_zero_acc() { if (threadIdx.x < 16) g_acc[threadIdx.x] = 0.0; }

__global__ void k_zero_vec(float* v, int n) {
    int i = blockIdx.x * blockDim.x + threadIdx.x;
    if (i < n) v[i] = 0.f;
}

__global__ void k_rownorm(const float* __restrict__ in, float* __restrict__ out, int cols) {
    int row = blockIdx.x;
    const float* r = in + (size_t)row * cols;
    float ss = 0.f;
    for (int c = threadIdx.x; c < cols; c += blockDim.x) { float x = r[c]; ss += x * x; }
    float tot = blockReduceSum(ss);
    __shared__ float sInv;
    if (threadIdx.x == 0) sInv = 1.f / fmaxf(sqrtf(tot), CLAMPF);
    __syncthreads();
    float inv = sInv;
    float* o = out + (size_t)row * cols;
    for (int c = threadIdx.x; c < cols; c += blockDim.x) o[c] = r[c] * inv;
}

// Xn = X / clamp(sqrt(rowdot(X, XS)))
__global__ void k_metricnorm(const float* __restrict__ X, const float* __restrict__ XS,
                             float* __restrict__ Xn, int cols) {
    int row = blockIdx.x;
    const float* r  = X  + (size_t)row * cols;
    const float* rs = XS + (size_t)row * cols;
    float ss = 0.f;
    for (int c = threadIdx.x; c < cols; c += blockDim.x) ss += r[c] * rs[c];
    float tot = blockReduceSum(ss);
    __shared__ float sInv;
    if (threadIdx.x == 0) sInv = 1.f / fmaxf(sqrtf(tot), CLAMPF);
    __syncthreads();
    float inv = sInv;
    float* o = Xn + (size_t)row * cols;
    for (int c = threadIdx.x; c < cols; c += blockDim.x) o[c] = r[c] * inv;
}

__global__ void k_rowscale(const float* __restrict__ in, const float* __restrict__ s,
                           float* __restrict__ out, int C, size_t n) {
    for (size_t idx = (size_t)blockIdx.x * blockDim.x + threadIdx.x; idx < n;
         idx += (size_t)gridDim.x * blockDim.x) {
        int i = (int)(idx / C);
        out[idx] = in[idx] * s[i];
    }
}

// ---------------- GEMM: C = alpha * op(A) @ op(B) ----------------
// logical A is MxK: TA ? stored KxM : stored MxK (row-major)
// logical B is KxN: TB ? stored NxK : stored KxN
// M,N multiples of 128; K multiple of 8. gridDim.z = split-K factor;
// block z handles k in [z*Kc, (z+1)*Kc) and writes slice z of C (M*N each).
// Double-buffered SMEM, register-staged prefetch, 1 sync per k-tile.
// Inner loop uses packed fma.rn.f32x2 (2 fp32 FMA per instruction).
template<bool TA, bool TB>
__global__ void __launch_bounds__(256, 2)
k_gemm(const float* __restrict__ A, const float* __restrict__ B,
       float* __restrict__ C, int M, int N, int K, int Kc, float alpha) {
    __shared__ alignas(16) float As[2][8][132];
    __shared__ alignas(16) float Bs[2][8][132];
    int bm = blockIdx.y * 128, bn = blockIdx.x * 128;
    int kb = blockIdx.z * Kc;
    C += (size_t)blockIdx.z * M * N;
    int tid = threadIdx.x;
    int tx = tid & 15, ty = tid >> 4;   // 16x16 threads

    float2 accP[8][4];                  // packed along j: accP[i][jp] = {c(i,2jp), c(i,2jp+1)}
    #pragma unroll
    for (int i = 0; i < 8; i++)
        #pragma unroll
        for (int jp = 0; jp < 4; jp++) accP[i][jp] = make_float2(0.f, 0.f);

    float sA[4];     // staging (scalar path)
    float4 sA4;      // staging (vector path)
    float sB[4];
    float4 sB4;

    auto loadA = [&](int k0) {
        if (!TA) {
            int k = tid & 7, m0 = tid >> 3;
            #pragma unroll
            for (int r = 0; r < 4; r++)
                sA[r] = A[(size_t)(bm + m0 + r * 32) * K + (k0 + k)];
        } else {
            int k = tid >> 5, m4 = (tid & 31) * 4;
            sA4 = *reinterpret_cast<const float4*>(&A[(size_t)(k0 + k) * M + bm + m4]);
        }
    };
    auto storeA = [&](int b) {
        if (!TA) {
            int k = tid & 7, m0 = tid >> 3;
            #pragma unroll
            for (int r = 0; r < 4; r++) As[b][k][m0 + r * 32] = sA[r];
        } else {
            int k = tid >> 5, m4 = (tid & 31) * 4;
            *reinterpret_cast<float4*>(&As[b][k][m4]) = sA4;
        }
    };
    auto loadB = [&](int k0) {
        if (!TB) {
            int k = tid >> 5, n4 = (tid & 31) * 4;
            sB4 = *reinterpret_cast<const float4*>(&B[(size_t)(k0 + k) * N + bn + n4]);
        } else {
            int k = tid & 7, n0 = tid >> 3;
            #pragma unroll
            for (int r = 0; r < 4; r++)
                sB[r] = B[(size_t)(bn + n0 + r * 32) * K + (k0 + k)];
        }
    };
    auto storeB = [&](int b) {
        if (!TB) {
            int k = tid >> 5, n4 = (tid & 31) * 4;
            *reinterpret_cast<float4*>(&Bs[b][k][n4]) = sB4;
        } else {
            int k = tid & 7, n0 = tid >> 3;
            #pragma unroll
            for (int r = 0; r < 4; r++) Bs[b][k][n0 + r * 32] = sB[r];
        }
    };

    loadA(kb); loadB(kb);
    storeA(0); storeB(0);
    __syncthreads();
    int buf = 0;
    for (int k0 = kb; k0 < kb + Kc; k0 += 8) {
        bool more = (k0 + 8 < kb + Kc);
        if (more) { loadA(k0 + 8); loadB(k0 + 8); }
        #pragma unroll
        for (int k = 0; k < 8; k++) {
            const float4* ap = reinterpret_cast<const float4*>(&As[buf][k][ty * 8]);
            const float4* bp = reinterpret_cast<const float4*>(&Bs[buf][k][tx * 8]);
            float4 a0 = ap[0], a1 = ap[1];
            float4 b0 = bp[0], b1 = bp[1];
            float ra[8] = {a0.x, a0.y, a0.z, a0.w, a1.x, a1.y, a1.z, a1.w};
            float2 rbP[4] = {make_float2(b0.x, b0.y), make_float2(b0.z, b0.w),
                             make_float2(b1.x, b1.y), make_float2(b1.z, b1.w)};
            #pragma unroll
            for (int i = 0; i < 8; i++) {
                float2 aa = make_float2(ra[i], ra[i]);
                #pragma unroll
                for (int jp = 0; jp < 4; jp++)
                    accP[i][jp] = ffma2(aa, rbP[jp], accP[i][jp]);
            }
        }
        if (more) {
            storeA(buf ^ 1); storeB(buf ^ 1);
            __syncthreads();
            buf ^= 1;
        }
    }
    #pragma unroll
    for (int i = 0; i < 8; i++) {
        int gm = bm + ty * 8 + i;
        float* cp = &C[(size_t)gm * N + bn + tx * 8];
        float4 o0 = make_float4(alpha * accP[i][0].x, alpha * accP[i][0].y,
                                alpha * accP[i][1].x, alpha * accP[i][1].y);
        float4 o1 = make_float4(alpha * accP[i][2].x, alpha * accP[i][2].y,
                                alpha * accP[i][3].x, alpha * accP[i][3].y);
        reinterpret_cast<float4*>(cp)[0] = o0;
        reinterpret_cast<float4*>(cp)[1] = o1;
    }
}

// Sum S slices of the split-K workspace into C (deterministic order).
__global__ void k_sk_reduce(const float* __restrict__ W, float* __restrict__ C,
                            size_t mn, int S) {
    for (size_t i = (size_t)blockIdx.x * blockDim.x + threadIdx.x; i < mn;
         i += (size_t)gridDim.x * blockDim.x) {
        float s = 0.f;
        for (int k = 0; k < S; k++) s += W[(size_t)k * mn + i];
        C[i] = s;
    }
}

// ---------------- Sinkhorn (log-domain, fixed-shift LSE) ----------------
// M = 20*cos is bounded in [-20,20]; u,v stay O(10), so exp args stay ~<=21:
// no overflow possible in float. Plain sum-of-exp replaces online max-tracking.
__global__ void k_row_lse(const float* __restrict__ M, const float* __restrict__ v,
                          float* __restrict__ u, int C, float log_a) {
    int row = blockIdx.x;
    const float4* r4 = reinterpret_cast<const float4*>(M + (size_t)row * C);
    const float4* v4 = reinterpret_cast<const float4*>(v);
    int n4 = C >> 2;
    float s = 0.f;
    for (int c = threadIdx.x; c < n4; c += blockDim.x) {
        float4 m = r4[c], vv = v4[c];
        s += __expf(m.x + vv.x) + __expf(m.y + vv.y)
           + __expf(m.z + vv.z) + __expf(m.w + vv.w);
    }
    float tot = blockReduceSum(s);
    if (threadIdx.x == 0) u[row] = log_a - logf(tot);
}

__global__ void k_col_lse_part(const float* __restrict__ M, const float* __restrict__ u,
                               float* __restrict__ ps, int C, int chunk) {
    int col = blockIdx.x * blockDim.x + threadIdx.x;
    int r0 = blockIdx.y * chunk;
    float s = 0.f;
    for (int r = r0; r < r0 + chunk; r++) s += __expf(M[(size_t)r * C + col] + u[r]);
    ps[(size_t)blockIdx.y * C + col] = s;
}

__global__ void k_col_lse_comb(const float* __restrict__ ps, float* __restrict__ v,
                               int C, int splits, float log_b) {
    int col = blockIdx.x * blockDim.x + threadIdx.x;
    if (col >= C) return;
    float s = 0.f;
    for (int k = 0; k < splits; k++) s += ps[(size_t)k * C + col];
    v[col] = log_b - logf(s);
}

// P = exp(M + u_i + v_j); shift/mask for pow2 column count
__global__ void k_plan(const float* __restrict__ M, const float* __restrict__ u,
                       const float* __restrict__ v, float* __restrict__ P,
                       int shift, int mask, size_t n) {
    for (size_t idx = (size_t)blockIdx.x * blockDim.x + threadIdx.x; idx < n;
         idx += (size_t)gridDim.x * blockDim.x) {
        int i = (int)(idx >> shift), j = (int)(idx & mask);
        P[idx] = __expf(M[idx] + u[i] + v[j]);
    }
}

__global__ void k_rowsum(const float* __restrict__ P, float* __restrict__ rs, int C) {
    int row = blockIdx.x;
    const float* r = P + (size_t)row * C;
    float s = 0.f;
    for (int c = threadIdx.x; c < C; c += blockDim.x) s += r[c];
    float tot = blockReduceSum(s);
    if (threadIdx.x == 0) rs[row] = tot;
}

__global__ void k_colsum_part(const float* __restrict__ P, float* __restrict__ part,
                              int C, int chunk) {
    int col = blockIdx.x * blockDim.x + threadIdx.x;
    int r0 = blockIdx.y * chunk;
    float s = 0.f;
    for (int r = r0; r < r0 + chunk; r++) s += P[(size_t)r * C + col];
    part[(size_t)blockIdx.y * C + col] = s;
}

__global__ void k_colsum_comb(const float* __restrict__ part, float* __restrict__ cs,
                              int C, int splits) {
    int col = blockIdx.x * blockDim.x + threadIdx.x;
    if (col >= C) return;
    float s = 0.f;
    for (int k = 0; k < splits; k++) s += part[(size_t)k * C + col];
    cs[col] = s;
}

// row sums of exp(M + u_i + v_j), no plan materialization (pair plan)
__global__ void k_exp_rowsum(const float* __restrict__ M, const float* __restrict__ u,
                             const float* __restrict__ v, float* __restrict__ rs, int C) {
    int row = blockIdx.x;
    const float* r = M + (size_t)row * C;
    float uu = u[row];
    float s = 0.f;
    for (int c = threadIdx.x; c < C; c += blockDim.x) s += __expf(r[c] + uu + v[c]);
    float tot = blockReduceSum(s);
    if (threadIdx.x == 0) rs[row] = tot;
}

__global__ void k_exp_colsum_part(const float* __restrict__ M, const float* __restrict__ u,
                                  const float* __restrict__ v, float* __restrict__ part,
                                  int C, int chunk) {
    int col = blockIdx.x * blockDim.x + threadIdx.x;
    int r0 = blockIdx.y * chunk;
    float vv = v[col];
    float s = 0.f;
    for (int r = r0; r < r0 + chunk; r++) s += __expf(M[(size_t)r * C + col] + u[r] + vv);
    part[(size_t)blockIdx.y * C + col] = s;
}

// ---------------- loss reductions ----------------
__global__ void k_marg(const float* __restrict__ s, int n) {
    float inv = 1.f / (float)n;
    float local = 0.f;
    for (int i = blockIdx.x * blockDim.x + threadIdx.x; i < n; i += gridDim.x * blockDim.x) {
        float d = s[i] - inv; local += d * d;
    }
    float tot = blockReduceSum(local);
    if (threadIdx.x == 0) atomicAdd(&g_acc[0], (double)tot);
}

// sail / exp / imp over the pair cost matrix
__global__ void k_pair_losses(const float* __restrict__ Mp, const float* __restrict__ u,
                              const float* __restrict__ v) {
    float sail = 0.f, expd = 0.f, impd = 0.f;
    const size_t n = (size_t)NP * NP;
    for (size_t idx = (size_t)blockIdx.x * blockDim.x + threadIdx.x; idx < n;
         idx += (size_t)gridDim.x * blockDim.x) {
        int i = (int)(idx >> 11), j = (int)(idx & 2047);
        float mval = Mp[idx];
        float cosv = mval * 0.05f;                 // Mp = 20*cos
        float z = (i == j) ? cosv * 10.f : -cosv * 10.f;
        float x = -z;                              // softplus(-z) = -log_sigmoid(z)
        float sp = (x > 0.f) ? x + log1pf(__expf(-x)) : log1pf(__expf(x));
        sail += sp;
        if (i == j) {
            expd += (1.f - cosv) * 0.5f;
            impd += mval + u[i] + v[j];
        }
    }
    float t;
    t = blockReduceSum(sail); if (threadIdx.x == 0) atomicAdd(&g_acc[1], (double)t);
    t = blockReduceSum(expd); if (threadIdx.x == 0) atomicAdd(&g_acc[2], (double)t);
    t = blockReduceSum(impd); if (threadIdx.x == 0) atomicAdd(&g_acc[3], (double)t);
}

// L_ot = sum( exp(logp_a) * (logp_a - logp_u) )
__global__ void k_ot(const float* __restrict__ Ma, const float* __restrict__ ua,
                     const float* __restrict__ va, const float* __restrict__ Mu,
                     const float* __restrict__ uu, const float* __restrict__ vu) {
    float local = 0.f;
    const size_t n = (size_t)NN * NN;
    for (size_t idx = (size_t)blockIdx.x * blockDim.x + threadIdx.x; idx < n;
         idx += (size_t)gridDim.x * blockDim.x) {
        int i = (int)(idx >> 12), j = (int)(idx & 4095);
        float lpa = Ma[idx] + ua[i] + va[j];
        float lpu = Mu[idx] + uu[i] + vu[j];
        local += __expf(lpa) * (lpa - lpu);
    }
    float tot = blockReduceSum(local);
    if (threadIdx.x == 0) atomicAdd(&g_acc[4], (double)tot);
}

__global__ void k_dot(const float* __restrict__ A, const float* __restrict__ B,
                      size_t n, int slot) {
    float local = 0.f;
    for (size_t i = (size_t)blockIdx.x * blockDim.x + threadIdx.x; i < n;
         i += (size_t)gridDim.x * blockDim.x) local += A[i] * B[i];
    float tot = blockReduceSum(local);
    if (threadIdx.x == 0) atomicAdd(&g_acc[slot], (double)tot);
}

__global__ void k_final(float* out) {
    double Npd = 2048.0;
    double cste = 4096.0 * 4096.0;
    double L = g_acc[0]
             + g_acc[1] / (Npd * Npd)
             + g_acc[2] / Npd
             + (-(g_acc[3]) / Npd - log(Npd))
             + g_acc[4]
             + (g_acc[5] + g_acc[6] - 2.0 * g_acc[7]) / cste
             + (g_acc[8] + g_acc[9] - 2.0 * g_acc[10]);
    out[0] = (float)L;
}

// ---------------- host-side helpers ----------------
static inline float* sym(const void* s) {
    void* p = nullptr;
    cudaGetSymbolAddress(&p, s);
    return (float*)p;
}

// S = split-K factor (K % S == 0 and (K/S) % 8 == 0 required).
static inline void gemm(const float* A, const float* B, float* C,
                        int M, int N, int K, float alpha, bool ta, bool tb, int S = 1) {
    float* out = C;
    if (S > 1) out = sym(g_skw);
    int Kc = K / S;
    dim3 g(N / 128, M / 128, S), b(256);
    if (!ta && !tb)      k_gemm<false, false><<<g, b>>>(A, B, out, M, N, K, Kc, alpha);
    else if (ta && !tb)  k_gemm<true,  false><<<g, b>>>(A, B, out, M, N, K, Kc, alpha);
    else if (!ta && tb)  k_gemm<false, true ><<<g, b>>>(A, B, out, M, N, K, Kc, alpha);
    else                 k_gemm<true,  true ><<<g, b>>>(A, B, out, M, N, K, Kc, alpha);
    if (S > 1) {
        size_t mn = (size_t)M * N;
        int blocks = (int)((mn + 255) / 256);
        if (blocks > 1024) blocks = 1024;
        k_sk_reduce<<<blocks, 256>>>(out, C, mn, S);
    }
}

static inline void run_sinkhorn(const float* M, float* u, float* v, int R, int C,
                                float* ps) {
    float log_a = -logf((float)R), log_b = -logf((float)C);
    const int splits = 32;
    int chunk = R / splits;
    k_zero_vec<<<(C + 255) / 256, 256>>>(v, C);
    for (int it = 0; it < 10; it++) {
        k_row_lse<<<R, 256>>>(M, v, u, C, log_a);
        dim3 g(C / 256, splits);
        k_col_lse_part<<<g, 256>>>(M, u, ps, C, chunk);
        k_col_lse_comb<<<(C + 255) / 256, 256>>>(ps, v, C, splits, log_b);
    }
}

extern "C" void kernel_launch(void* const* d_in, const int* in_sizes, int n_in,
                              void* d_out, int out_size) {
    const float* fXp = (const float*)d_in[0];
    const float* fYp = (const float*)d_in[1];
    const float* X   = (const float*)d_in[2];
    const float* Y   = (const float*)d_in[3];
    const float* fX  = (const float*)d_in[4];
    const float* fY  = (const float*)d_in[5];
    const float* Xan = (const float*)d_in[6];
    const float* Yan = (const float*)d_in[7];
    float* out = (float*)d_out;

    float *pXa = sym(g_Xa), *pYa = sym(g_Ya);
    float *pSxx = sym(g_Sxx), *pSyy = sym(g_Syy), *pSxy = sym(g_Sxy);
    float *pfXp = sym(g_fXp), *pfYp = sym(g_fYp);
    float *pMp = sym(g_Mp);
    float *pfXn = sym(g_fXn), *pfYn = sym(g_fYn);
    float *pMu = sym(g_Mu), *pMa = sym(g_Ma), *pP = sym(g_P);
    float *pXS = sym(g_XS), *pYS = sym(g_YS);
    float *pXn = sym(g_Xn), *pYn = sym(g_Yn);
    float *pXu = sym(g_Xu), *pYu = sym(g_Yu);
    float *pT = sym(g_T);
    float *pCxx = sym(g_Cxx), *pCyy = sym(g_Cyy);
    float *pU1 = sym(g_U1), *pV1 = sym(g_V1);
    float *pFxx = sym(g_Fxx), *pFyy = sym(g_Fyy);
    float *pW1 = sym(g_W1), *pW2 = sym(g_W2), *pW3 = sym(g_W3);
    float *pMA = sym(g_MA);
    float *pu1 = sym(g_u1), *pv1 = sym(g_v1);
    float *pu2 = sym(g_u2), *pv2 = sym(g_v2);
    float *pu3 = sym(g_u3), *pv3 = sym(g_v3);
    float *ppm = sym(g_pm), *pps = sym(g_ps);
    float *prsp = sym(g_rsp), *pcsp = sym(g_csp);
    float *pa = sym(g_a), *pb = sym(g_b);

    k_zero_acc<<<1, 32>>>();

    // ---- anchor covariances ----
    k_rownorm<<<NN, 256>>>(Xan, pXa, DX);
    k_rownorm<<<NN, 256>>>(Yan, pYa, DY);
    const float invN = 1.0f / (float)NN;
    gemm(pXa, pXa, pSxx, DX, DX, NN, invN, true, false, 8);
    gemm(pYa, pYa, pSyy, DY, DY, NN, invN, true, false, 8);
    gemm(pXa, pYa, pSxy, DX, DY, NN, invN, true, false, 8);

    // ---- cost matrices (M = cos/eps = 20*cos) ----
    k_rownorm<<<NP, 256>>>(fXp, pfXp, DF);
    k_rownorm<<<NP, 256>>>(fYp, pfYp, DF);
    gemm(pfXp, pfYp, pMp, NP, NP, DF, EPS_INV, false, true);
    k_rownorm<<<NN, 256>>>(fX, pfXn, DF);
    k_rownorm<<<NN, 256>>>(fY, pfYn, DF);
    gemm(pfXn, pfYn, pMu, NN, NN, DF, EPS_INV, false, true);

    // ---- sinkhorns (pairs + latent) ----
    run_sinkhorn(pMp, pu1, pv1, NP, NP, pps);
    run_sinkhorn(pMu, pu2, pv2, NN, NN, pps);

    // ---- plan_p marginals (exp fused, no plan materialization) + pair losses ----
    k_exp_rowsum<<<NP, 256>>>(pMp, pu1, pv1, prsp, NP);
    {
        dim3 g(NP / 256, 32);
        k_exp_colsum_part<<<g, 256>>>(pMp, pu1, pv1, ppm, NP, NP / 32);
        k_colsum_comb<<<(NP + 255) / 256, 256>>>(ppm, pcsp, NP, 32);
    }
    k_marg<<<(NP + 255) / 256, 256>>>(prsp, NP);
    k_marg<<<(NP + 255) / 256, 256>>>(pcsp, NP);
    k_pair_losses<<<4096, 256>>>(pMp, pu1, pv1);

    // ---- plan_u: materialize (needed for P@Yu) + marginals ----
    k_plan<<<4096, 256>>>(pMu, pu2, pv2, pP, 12, 4095, (size_t)NN * NN);
    k_rowsum<<<NN, 256>>>(pP, pa, NN);
    {
        dim3 g(NN / 256, 32);
        k_colsum_part<<<g, 256>>>(pP, ppm, NN, NN / 32);
        k_colsum_comb<<<(NN + 255) / 256, 256>>>(ppm, pb, NN, 32);
    }
    k_marg<<<(NN + 255) / 256, 256>>>(pa, NN);
    k_marg<<<(NN + 255) / 256, 256>>>(pb, NN);

    // ---- anchor-space plan ----
    gemm(X, pSxx, pXS, NN, DX, DX, 1.0f, false, false);           // grid 192
    k_metricnorm<<<NN, 256>>>(X, pXS, pXn, DX);
    gemm(Y, pSyy, pYS, NN, DY, DY, 1.0f, false, false, 2);        // 128 -> 256
    k_metricnorm<<<NN, 256>>>(Y, pYS, pYn, DY);
    gemm(pXn, pSxy, pT, NN, DY, DX, 1.0f, false, false, 2);       // 128 -> 256
    gemm(pT, pYn, pMa, NN, NN, DY, EPS_INV, false, true);         // grid 1024
    run_sinkhorn(pMa, pu3, pv3, NN, NN, pps);
    k_ot<<<4096, 256>>>(pMa, pu3, pv3, pMu, pu2, pv2);

    // ---- L_div ----
    gemm(pXn, pXn, pCxx, DX, DX, NN, 1.0f, true, false, 8);
    gemm(pYn, pYn, pCyy, DY, DY, NN, 1.0f, true, false, 8);
    gemm(pCxx, pSxy, pU1, DX, DY, DX, 1.0f, false, false, 6);     // Kc=128
    gemm(pU1, pCyy, pV1, DX, DY, DY, 1.0f, false, false, 8);      // Kc=64
    k_dot<<<1024, 256>>>(pV1, pSxy, (size_t)DX * DY, 5);
    gemm(pfXn, pfXn, pFxx, DF, DF, NN, 1.0f, true, false, 32);    // 4 -> 128
    gemm(pfYn, pfYn, pFyy, DF, DF, NN, 1.0f, true, false, 32);
    k_dot<<<256, 256>>>(pFxx, pFyy, (size_t)DF * DF, 6);
    gemm(pXn, pfXn, pW1, DX, DF, NN, 1.0f, true, false, 16);      // 12 -> 192
    gemm(pfYn, pYn, pW2, DF, DY, NN, 1.0f, true, false, 16);      // 8 -> 128
    gemm(pW1, pW2, pW3, DX, DY, DF, 1.0f, false, false, 8);       // Kc=32
    k_dot<<<1024, 256>>>(pW3, pSxy, (size_t)DX * DY, 7);

    // ---- L_gw (factored; Kx/Ky never materialized) ----
    k_rownorm<<<NN, 256>>>(X, pXu, DX);
    k_rownorm<<<NN, 256>>>(Y, pYu, DY);
    // aKx^2a = || Xu^T diag(a) Xu ||_F^2
    k_rowscale<<<4096, 256>>>(pXu, pa, pXS, DX, (size_t)NN * DX);
    gemm(pXu, pXS, pMA, DX, DX, NN, 1.0f, true, false, 8);
    k_dot<<<1024, 256>>>(pMA, pMA, (size_t)DX * DX, 8);
    // bKy^2b = || Yu^T diag(b) Yu ||_F^2
    k_rowscale<<<4096, 256>>>(pYu, pb, pYS, DY, (size_t)NN * DY);
    gemm(pYu, pYS, pMA, DY, DY, NN, 1.0f, true, false, 8);
    k_dot<<<1024, 256>>>(pMA, pMA, (size_t)DY * DY, 9);
    // cross term = || Xu^T P Yu ||_F^2
    gemm(pP, pYu, pT, NN, DY, NN, 1.0f, false, false, 2);         // 128 -> 256
    gemm(pXu, pT, pMA, DX, DY, NN, 1.0f, true, false, 8);         // 24 -> 192
    k_dot<<<1024, 256>>>(pMA, pMA, (size_t)DX * DY, 10);

    // ---- combine ----
    k_final<<<1, 1>>>(out);
}